// round 1
// baseline (speedup 1.0000x reference)
#include <cuda_runtime.h>

#define NN 50000
#define NE 800000
#define FIN 128
#define DD 64
#define HH 4
#define HD 256   // H*D
#define EDIM 20

// ---------------- scratch (device globals; no allocation allowed) ----------
__device__ float g_h[NN * DD];        // 12.8 MB current node features
__device__ float g_e[NE * EDIM];      // 64 MB edge embeddings
__device__ float g_ee[NE * HD];       // 819 MB  e_emb @ We  (layer-invariant)
__device__ float g_xl[NN * HD];       // 51.2 MB
__device__ float g_xr[NN * HD];       // 51.2 MB
__device__ float g_score[NE * HH];    // 12.8 MB (scores, then exp values)
__device__ float g_smax[NN * HH];
__device__ float g_den[NN * HH];
__device__ float g_out[NN * HD];      // 51.2 MB

// ---------------- helpers ----------------
__device__ __forceinline__ void atomicMaxF(float* addr, float v) {
    // valid for init = -inf; standard signed/unsigned bit-trick
    if (v >= 0.f) atomicMax((int*)addr, __float_as_int(v));
    else          atomicMin((unsigned int*)addr, __float_as_uint(v));
}

__device__ __forceinline__ void red_add_v4(float* p, float4 v) {
    asm volatile("red.global.add.v4.f32 [%0], {%1,%2,%3,%4};"
                 :: "l"(p), "f"(v.x), "f"(v.y), "f"(v.z), "f"(v.w) : "memory");
}

// ---------------- h0 = relu(x @ f_W + f_b) ----------------
// block 256 = 4 rows x 64 cols
__global__ void k_h0(const float* __restrict__ x, const float* __restrict__ fW,
                     const float* __restrict__ fb) {
    __shared__ float Ws[FIN * DD];   // 32 KB
    __shared__ float xs[4][FIN];     // 2 KB
    int t = threadIdx.x;
    for (int i = t; i < FIN * DD; i += 256) Ws[i] = fW[i];
    int n0 = blockIdx.x * 4;
    for (int i = t; i < 4 * FIN; i += 256) {
        int r = i / FIN, k = i % FIN;
        int n = n0 + r;
        xs[r][k] = (n < NN) ? x[n * FIN + k] : 0.f;
    }
    __syncthreads();
    int r = t >> 6, d = t & 63;
    int n = n0 + r;
    if (n < NN) {
        float acc = fb[d];
#pragma unroll 8
        for (int k = 0; k < FIN; k++) acc = fmaf(xs[r][k], Ws[k * DD + d], acc);
        g_h[n * DD + d] = fmaxf(acc, 0.f);
    }
}

// ---------------- e = relu(edge_attr @ fe_W + fe_b) ----------------
__global__ void k_eemb(const float* __restrict__ ea, const float* __restrict__ feW,
                       const float* __restrict__ feb) {
    int e = blockIdx.x * blockDim.x + threadIdx.x;
    if (e >= NE) return;
    float a0 = ea[e * 2], a1 = ea[e * 2 + 1];
#pragma unroll
    for (int j = 0; j < EDIM; j++) {
        float v = fmaf(a0, __ldg(&feW[j]), fmaf(a1, __ldg(&feW[EDIM + j]), __ldg(&feb[j])));
        g_e[e * EDIM + j] = fmaxf(v, 0.f);
    }
}

// ---------------- ee = e @ We  (once; layer invariant) ----------------
// block (32,8): lane -> 8 cols (2 float4), ty -> 4 edges. 32 edges x 256 cols per block.
__global__ void k_ee(const float* __restrict__ We) {
    __shared__ float4 Ws4[EDIM][64];   // 20 KB
    __shared__ float  es[32][EDIM + 1];
    int t = threadIdx.y * 32 + threadIdx.x;
    for (int i = t; i < EDIM * 64; i += 256)
        Ws4[i / 64][i % 64] = ((const float4*)We)[i];
    int e0 = blockIdx.x * 32;
    for (int i = t; i < 32 * EDIM; i += 256) {
        int r = i / EDIM, k = i % EDIM;
        es[r][k] = g_e[(e0 + r) * EDIM + k];
    }
    __syncthreads();
    int lane = threadIdx.x, ty = threadIdx.y;
    float4 a0[4], a1[4];
#pragma unroll
    for (int r = 0; r < 4; r++) { a0[r] = make_float4(0,0,0,0); a1[r] = make_float4(0,0,0,0); }
#pragma unroll
    for (int k = 0; k < EDIM; k++) {
        float4 w0 = Ws4[k][lane * 2];
        float4 w1 = Ws4[k][lane * 2 + 1];
#pragma unroll
        for (int r = 0; r < 4; r++) {
            float ev = es[ty * 4 + r][k];
            a0[r].x = fmaf(ev, w0.x, a0[r].x); a0[r].y = fmaf(ev, w0.y, a0[r].y);
            a0[r].z = fmaf(ev, w0.z, a0[r].z); a0[r].w = fmaf(ev, w0.w, a0[r].w);
            a1[r].x = fmaf(ev, w1.x, a1[r].x); a1[r].y = fmaf(ev, w1.y, a1[r].y);
            a1[r].z = fmaf(ev, w1.z, a1[r].z); a1[r].w = fmaf(ev, w1.w, a1[r].w);
        }
    }
#pragma unroll
    for (int r = 0; r < 4; r++) {
        int e = e0 + ty * 4 + r;
        float4* dst = (float4*)(g_ee + (size_t)e * HD);
        dst[lane * 2]     = a0[r];
        dst[lane * 2 + 1] = a1[r];
    }
}

// ---------------- per-layer init ----------------
__global__ void k_init() {
    int i = blockIdx.x * blockDim.x + threadIdx.x;
    int stride = gridDim.x * blockDim.x;
    for (int j = i; j < NN * HD; j += stride) g_out[j] = 0.f;
    for (int j = i; j < NN * HH; j += stride) {
        g_smax[j] = __int_as_float(0xff800000u);  // -inf
        g_den[j]  = 0.f;
    }
}

// ---------------- xl = h@Wl+bl, xr = h@Wr+br ----------------
// grid (ceil(N/32), 4 col-tiles of 128). block (32,8).
__global__ void k_lin(const float* __restrict__ Wl, const float* __restrict__ bl,
                      const float* __restrict__ Wr, const float* __restrict__ br) {
    __shared__ float4 Ws[DD][32];      // 64 x 128 floats = 32 KB
    __shared__ float  hs[32][DD];      // 8 KB
    int t = threadIdx.y * 32 + threadIdx.x;
    int tile_c = blockIdx.y * 128;                 // 0,128,256,384
    const float* W  = (tile_c < HD) ? Wl : Wr;
    const float* bb = (tile_c < HD) ? bl : br;
    int cb = tile_c & (HD - 1);                    // 0 or 128
    for (int i = t; i < DD * 32; i += 256) {
        int k = i / 32, q = i % 32;
        Ws[k][q] = ((const float4*)(W + k * HD + cb))[q];
    }
    int n0 = blockIdx.x * 32;
    for (int i = t; i < 32 * DD; i += 256) {
        int r = i / DD, k = i % DD;
        int n = n0 + r;
        hs[r][k] = (n < NN) ? g_h[n * DD + k] : 0.f;
    }
    __syncthreads();
    int lane = threadIdx.x, ty = threadIdx.y;
    float4 bv = ((const float4*)(bb + cb))[lane];
    float4 acc[4];
#pragma unroll
    for (int q = 0; q < 4; q++) acc[q] = bv;
#pragma unroll 16
    for (int k = 0; k < DD; k++) {
        float4 w = Ws[k][lane];
#pragma unroll
        for (int q = 0; q < 4; q++) {
            float hv = hs[ty * 4 + q][k];
            acc[q].x = fmaf(hv, w.x, acc[q].x);
            acc[q].y = fmaf(hv, w.y, acc[q].y);
            acc[q].z = fmaf(hv, w.z, acc[q].z);
            acc[q].w = fmaf(hv, w.w, acc[q].w);
        }
    }
    float* outp = (tile_c < HD) ? g_xl : g_xr;
#pragma unroll
    for (int q = 0; q < 4; q++) {
        int n = n0 + ty * 4 + q;
        if (n < NN) ((float4*)(outp + n * HD + cb))[lane] = acc[q];
    }
}

// ---------------- scores + segment max ----------------
// warp per edge; lane covers j = lane + 32*i; head h = i>>1.
__global__ void k_score(const int* __restrict__ ei, const float* __restrict__ att) {
    __shared__ float as[HD];
    int t = threadIdx.x;
    if (t < HD) as[t] = att[t];
    __syncthreads();
    int e = blockIdx.x * 8 + (t >> 5);
    int lane = t & 31;
    if (e >= NE) return;
    int src = ei[e], dst = ei[NE + e];
    const float* xl = g_xl + src * HD;
    const float* xr = g_xr + dst * HD;
    const float* ee = g_ee + (size_t)e * HD;
    float hs0 = 0.f, hs1 = 0.f, hs2 = 0.f, hs3 = 0.f;
#pragma unroll
    for (int i = 0; i < 8; i++) {
        int j = lane + 32 * i;
        float v = xl[j] + xr[j] + __ldcs(ee + j);
        v = v > 0.f ? v : 0.2f * v;
        float p = as[j] * v;
        if (i < 2) hs0 += p; else if (i < 4) hs1 += p;
        else if (i < 6) hs2 += p; else hs3 += p;
    }
#pragma unroll
    for (int o = 16; o; o >>= 1) {
        hs0 += __shfl_xor_sync(0xffffffffu, hs0, o);
        hs1 += __shfl_xor_sync(0xffffffffu, hs1, o);
        hs2 += __shfl_xor_sync(0xffffffffu, hs2, o);
        hs3 += __shfl_xor_sync(0xffffffffu, hs3, o);
    }
    if (lane == 0) {
        ((float4*)g_score)[e] = make_float4(hs0, hs1, hs2, hs3);
        atomicMaxF(&g_smax[dst * 4 + 0], hs0);
        atomicMaxF(&g_smax[dst * 4 + 1], hs1);
        atomicMaxF(&g_smax[dst * 4 + 2], hs2);
        atomicMaxF(&g_smax[dst * 4 + 3], hs3);
    }
}

// ---------------- exp + segment sum ----------------
__global__ void k_exp(const int* __restrict__ ei) {
    int e = blockIdx.x * blockDim.x + threadIdx.x;
    if (e >= NE) return;
    int dst = ei[NE + e];
    float4 s = ((float4*)g_score)[e];
    float4 m = ((float4*)g_smax)[dst];
    float e0 = __expf(s.x - m.x);
    float e1 = __expf(s.y - m.y);
    float e2 = __expf(s.z - m.z);
    float e3 = __expf(s.w - m.w);
    atomicAdd(&g_den[dst * 4 + 0], e0);
    atomicAdd(&g_den[dst * 4 + 1], e1);
    atomicAdd(&g_den[dst * 4 + 2], e2);
    atomicAdd(&g_den[dst * 4 + 3], e3);
    ((float4*)g_score)[e] = make_float4(e0, e1, e2, e3);
}

// ---------------- weighted aggregation ----------------
// warp per edge; lane covers 8 contiguous dims (one head per 8-lane group)
__global__ void k_agg(const int* __restrict__ ei) {
    int t = threadIdx.x;
    int e = blockIdx.x * 8 + (t >> 5);
    int lane = t & 31;
    if (e >= NE) return;
    int src = ei[e], dst = ei[NE + e];
    int h = lane >> 3;
    float ex  = g_score[e * 4 + h];
    float den = g_den[dst * 4 + h];
    float alpha = ex / den;
    const float4* xl = (const float4*)(g_xl + src * HD);
    float4 a = xl[lane * 2], b = xl[lane * 2 + 1];
    a.x *= alpha; a.y *= alpha; a.z *= alpha; a.w *= alpha;
    b.x *= alpha; b.y *= alpha; b.z *= alpha; b.w *= alpha;
    float* o = g_out + dst * HD + lane * 8;
    red_add_v4(o, a);
    red_add_v4(o + 4, b);
}

// ---------------- head mean + bias + relu ----------------
__global__ void k_final(const float* __restrict__ bias, float* __restrict__ dout, int writeOut) {
    int i = blockIdx.x * blockDim.x + threadIdx.x;
    if (i >= NN * DD) return;
    int n = i >> 6, d = i & 63;
    const float* o = g_out + n * HD;
    float v = 0.25f * (o[d] + o[64 + d] + o[128 + d] + o[192 + d]) + __ldg(&bias[d]);
    v = fmaxf(v, 0.f);
    if (writeOut) dout[i] = v;
    else          g_h[i] = v;
}

// ---------------- launch ----------------
extern "C" void kernel_launch(void* const* d_in, const int* in_sizes, int n_in,
                              void* d_out, int out_size) {
    const float* x   = (const float*)d_in[0];
    const float* ea  = (const float*)d_in[1];
    const int*   ei  = (const int*)  d_in[2];
    const float* fW  = (const float*)d_in[3];
    const float* fb  = (const float*)d_in[4];
    const float* feW = (const float*)d_in[5];
    const float* feb = (const float*)d_in[6];
    const float* Wl  = (const float*)d_in[7];
    const float* bl  = (const float*)d_in[8];
    const float* Wr  = (const float*)d_in[9];
    const float* br  = (const float*)d_in[10];
    const float* We  = (const float*)d_in[11];
    const float* att = (const float*)d_in[12];
    const float* bias= (const float*)d_in[13];

    k_h0<<<NN / 4, 256>>>(x, fW, fb);
    k_eemb<<<(NE + 255) / 256, 256>>>(ea, feW, feb);
    k_ee<<<NE / 32, dim3(32, 8)>>>(We);

    for (int l = 0; l < 3; l++) {
        k_init<<<2048, 256>>>();
        k_lin<<<dim3((NN + 31) / 32, 4), dim3(32, 8)>>>(Wl, bl, Wr, br);
        k_score<<<(NE + 7) / 8, 256>>>(ei, att);
        k_exp<<<(NE + 255) / 256, 256>>>(ei);
        k_agg<<<(NE + 7) / 8, 256>>>(ei);
        k_final<<<(NN * DD + 255) / 256, 256>>>(bias, (float*)d_out, l == 2 ? 1 : 0);
    }
}